// round 3
// baseline (speedup 1.0000x reference)
#include <cuda_runtime.h>
#include <cuda_bf16.h>
#include <cstdint>

// Problem dims
constexpr int BATCH    = 8192;
constexpr int IN_SIZE  = 4096;
constexpr int HIDDEN   = 4096;
constexpr int OUT_SIZE = 1024;
constexpr int K        = 4096;          // all three GEMMs reduce over 4096
constexpr int K2       = 2 * K;         // digit-concatenated K (int8 cols)

// GEMM tiling
constexpr int STAGES = 4;
constexpr int PITCH  = 144;             // 128B data + 16B pad (conflict-free ldmatrix)
constexpr int TILE_B = 128 * PITCH;     // one 128-row x 128-col int8 tile in smem
constexpr int STAGE_B = 2 * TILE_B;     // A + B
constexpr int SMEM_TOTAL = STAGES * STAGE_B;   // 147456

// ---------------- static device scratch ----------------
__device__ __align__(16) int8_t g_w1q[HIDDEN * K2];     // [4096][8192]
__device__ __align__(16) int8_t g_w2q[HIDDEN * K2];
__device__ __align__(16) int8_t g_w3q[OUT_SIZE * K2];
__device__ __align__(16) int8_t g_qa[BATCH * K2];       // digit activations
__device__ __align__(16) int8_t g_qb[BATCH * K2];
__device__ __align__(16) float  g_act[BATCH * HIDDEN];  // f32 inter-layer activations
__device__ float g_rowq[BATCH];
__device__ float g_part[3 * 2048];
__device__ float g_sum[3];

// ---------------- PTX helpers ----------------
__device__ __forceinline__ uint32_t sptr(const void* p) {
    return (uint32_t)__cvta_generic_to_shared(p);
}
__device__ __forceinline__ void cp16(uint32_t dst_smem, const void* src_gmem) {
    asm volatile("cp.async.cg.shared.global [%0], [%1], 16;\n" :: "r"(dst_smem), "l"(src_gmem));
}
__device__ __forceinline__ void ldsm4(uint32_t* r, uint32_t addr) {
    asm volatile("ldmatrix.sync.aligned.m8n8.x4.shared.b16 {%0,%1,%2,%3}, [%4];"
                 : "=r"(r[0]), "=r"(r[1]), "=r"(r[2]), "=r"(r[3]) : "r"(addr));
}
__device__ __forceinline__ void mma_s8(int32_t* d, const uint32_t* a, const uint32_t* b) {
    asm volatile(
        "mma.sync.aligned.m16n8k32.row.col.s32.s8.s8.s32 "
        "{%0,%1,%2,%3}, {%4,%5,%6,%7}, {%8,%9}, {%0,%1,%2,%3};"
        : "+r"(d[0]), "+r"(d[1]), "+r"(d[2]), "+r"(d[3])
        : "r"(a[0]), "r"(a[1]), "r"(a[2]), "r"(a[3]), "r"(b[0]), "r"(b[1]));
}

// ---------------- prep kernels ----------------
// weights: w -> dual-scaled signs in [N][2K] interleave: per 64-k chunk,
// bytes [0,64) = 64*sign(w), bytes [64,128) = sign(w). Plus |w| partial sums.
__global__ void sign_quant_kernel(const float4* __restrict__ w4,
                                  int8_t* __restrict__ out, int n4, int layer) {
    float s = 0.f;
    for (int i = blockIdx.x * blockDim.x + threadIdx.x; i < n4; i += gridDim.x * blockDim.x) {
        float4 v = w4[i];
        s += fabsf(v.x) + fabsf(v.y) + fabsf(v.z) + fabsf(v.w);
        int s0 = (v.x > 0.f) - (v.x < 0.f);
        int s1 = (v.y > 0.f) - (v.y < 0.f);
        int s2 = (v.z > 0.f) - (v.z < 0.f);
        int s3 = (v.w > 0.f) - (v.w < 0.f);
        int k   = (i * 4) & (K - 1);       // K = 4096, power of 2
        int row = (i * 4) >> 12;
        size_t off = (size_t)row * K2 + ((k >> 6) << 7) + (k & 63);
        uint32_t hp = (uint32_t)(uint8_t)(int8_t)(64 * s0)
                    | ((uint32_t)(uint8_t)(int8_t)(64 * s1) << 8)
                    | ((uint32_t)(uint8_t)(int8_t)(64 * s2) << 16)
                    | ((uint32_t)(uint8_t)(int8_t)(64 * s3) << 24);
        uint32_t lp = (uint32_t)(uint8_t)(int8_t)s0
                    | ((uint32_t)(uint8_t)(int8_t)s1 << 8)
                    | ((uint32_t)(uint8_t)(int8_t)s2 << 16)
                    | ((uint32_t)(uint8_t)(int8_t)s3 << 24);
        *reinterpret_cast<uint32_t*>(out + off)      = hp;
        *reinterpret_cast<uint32_t*>(out + off + 64) = lp;
    }
    __shared__ float red[256];
    red[threadIdx.x] = s;
    __syncthreads();
    for (int o = 128; o > 0; o >>= 1) {
        if (threadIdx.x < o) red[threadIdx.x] += red[threadIdx.x + o];
        __syncthreads();
    }
    if (threadIdx.x == 0) g_part[layer * 2048 + blockIdx.x] = red[0];
}

__global__ void finalize_sum_kernel() {
    __shared__ float red[1024];
    int l = blockIdx.x, t = threadIdx.x;
    red[t] = g_part[l * 2048 + t] + g_part[l * 2048 + 1024 + t];
    __syncthreads();
    for (int o = 512; o > 0; o >>= 1) {
        if (t < o) red[t] += red[t + o];
        __syncthreads();
    }
    if (t == 0) g_sum[l] = red[0];
}

// per-row quantize: f32 row -> per-row scale q + base-64 digits (h,l) interleaved
__global__ void quant_rows_kernel(const float* __restrict__ in,
                                  int8_t* __restrict__ out) {
    const int row = blockIdx.x;
    const float* r = in + (size_t)row * K;
    float m = 0.f;
    for (int k = threadIdx.x; k < K; k += 256) m = fmaxf(m, fabsf(r[k]));
    __shared__ float red[256];
    red[threadIdx.x] = m;
    __syncthreads();
    for (int o = 128; o > 0; o >>= 1) {
        if (threadIdx.x < o) red[threadIdx.x] = fmaxf(red[threadIdx.x], red[threadIdx.x + o]);
        __syncthreads();
    }
    const float q = red[0] * (1.0f / 8128.0f) + 1e-30f;
    if (threadIdx.x == 0) g_rowq[row] = q;
    const float inv64 = 1.0f / (64.0f * q);
    const float invq  = 1.0f / q;
    int8_t* o8 = out + (size_t)row * K2;
    for (int k = threadIdx.x; k < K; k += 256) {
        float v = r[k];
        float fh = rintf(v * inv64);
        fh = fminf(fmaxf(fh, -127.f), 127.f);
        float rem = v - fh * (64.0f * q);
        float fl = rintf(rem * invq);
        fl = fminf(fmaxf(fl, -127.f), 127.f);
        int off = ((k >> 6) << 7) + (k & 63);
        o8[off]      = (int8_t)(int)fh;
        o8[off + 64] = (int8_t)(int)fl;
    }
}

// ---------------- int8 digit-concat GEMM ----------------
// Y[M,N] = alpha * q_row * (Adig[M,2K] @ Bdig[N,2K]^T) + bias
// EPI 0: relu -> f32 g_act ; EPI 1: sigmoid -> f32 out
template <int EPI>
__global__ void __launch_bounds__(256, 1) gemm_i8(
    const int8_t* __restrict__ A, const int8_t* __restrict__ B,
    const float* __restrict__ bias, const float* __restrict__ sumAbs, float invCnt,
    int N, float* __restrict__ outF) {
    extern __shared__ __align__(128) int8_t smem[];
    const int tid  = threadIdx.x;
    const int lane = tid & 31;
    const int warp = tid >> 5;
    const int wm = warp & 3;   // 4 warps along M (32 rows)
    const int wn = warp >> 2;  // 2 warps along N (64 cols)
    const int bm = blockIdx.y, bn = blockIdx.x;
    constexpr int KT = K / 64;   // 64 iterations, 128 int8 cols each

    const int8_t* gA = A + (size_t)bm * 128 * K2;
    const int8_t* gB = B + (size_t)bn * 128 * K2;

    const int crow = tid >> 3;        // 0..31
    const int cchk = (tid & 7) * 16;  // 16B chunk within 128B row

    auto issue = [&](int kt, int s) {
        int8_t* st = smem + s * STAGE_B;
        const int kof = kt * 128;
        uint32_t sa = sptr(st);
        uint32_t sb = sptr(st + TILE_B);
#pragma unroll
        for (int rr = 0; rr < 4; rr++) {
            int row = rr * 32 + crow;
            cp16(sa + row * PITCH + cchk, gA + (size_t)row * K2 + kof + cchk);
            cp16(sb + row * PITCH + cchk, gB + (size_t)row * K2 + kof + cchk);
        }
    };

    int32_t acc[2][8][4];
#pragma unroll
    for (int i = 0; i < 2; i++)
#pragma unroll
        for (int j = 0; j < 8; j++)
#pragma unroll
            for (int v = 0; v < 4; v++) acc[i][j][v] = 0;

    // ldmatrix lane -> (row, byte-offset) mapping
    const int lrow = (lane & 7) + ((lane >> 3) & 1) * 8;
    const int lcof = (lane >> 4) * 16;

    auto compute = [&](int s) {
        const int8_t* st = smem + s * STAGE_B;
        const uint32_t sa = sptr(st);
        const uint32_t sb = sptr(st + TILE_B);
#pragma unroll
        for (int ks = 0; ks < 4; ks++) {
            uint32_t af[2][4], bf[8][2];
#pragma unroll
            for (int i = 0; i < 2; i++)
                ldsm4(af[i], sa + (wm * 32 + i * 16 + lrow) * PITCH + ks * 32 + lcof);
#pragma unroll
            for (int jj = 0; jj < 4; jj++) {
                uint32_t r[4];
                ldsm4(r, sb + (wn * 64 + jj * 16 + lrow) * PITCH + ks * 32 + lcof);
                bf[2 * jj][0] = r[0]; bf[2 * jj][1] = r[2];
                bf[2 * jj + 1][0] = r[1]; bf[2 * jj + 1][1] = r[3];
            }
#pragma unroll
            for (int i = 0; i < 2; i++)
#pragma unroll
                for (int j = 0; j < 8; j++) mma_s8(acc[i][j], af[i], bf[j]);
        }
    };

    // prologue: 3 stages ahead
    issue(0, 0);
    asm volatile("cp.async.commit_group;" ::: "memory");
    issue(1, 1);
    asm volatile("cp.async.commit_group;" ::: "memory");
    issue(2, 2);
    asm volatile("cp.async.commit_group;" ::: "memory");

    for (int kt = 0; kt < KT; kt++) {
        asm volatile("cp.async.wait_group 2;" ::: "memory");
        __syncthreads();
        int kn = kt + 3;
        if (kn < KT) issue(kn, kn & (STAGES - 1));
        asm volatile("cp.async.commit_group;" ::: "memory");
        compute(kt & (STAGES - 1));
    }

    // ---------------- epilogue ----------------
    const float alpha = __ldg(sumAbs) * invCnt;
    const int r0 = bm * 128 + wm * 32 + (lane >> 2);
    const int c0 = bn * 128 + wn * 64 + (lane & 3) * 2;
#pragma unroll
    for (int i = 0; i < 2; i++) {
        const int rowA = r0 + i * 16;
        const float qA = __ldg(g_rowq + rowA) * alpha;
        const float qB = __ldg(g_rowq + rowA + 8) * alpha;
#pragma unroll
        for (int j = 0; j < 8; j++) {
            const int col = c0 + j * 8;
            const float bx = __ldg(bias + col), by = __ldg(bias + col + 1);
            float v00 = (float)acc[i][j][0] * qA + bx;
            float v01 = (float)acc[i][j][1] * qA + by;
            float v10 = (float)acc[i][j][2] * qB + bx;
            float v11 = (float)acc[i][j][3] * qB + by;
            float2 p0, p1;
            if (EPI == 0) {
                p0.x = fmaxf(v00, 0.f); p0.y = fmaxf(v01, 0.f);
                p1.x = fmaxf(v10, 0.f); p1.y = fmaxf(v11, 0.f);
            } else {
                p0.x = 1.f / (1.f + __expf(-v00));
                p0.y = 1.f / (1.f + __expf(-v01));
                p1.x = 1.f / (1.f + __expf(-v10));
                p1.y = 1.f / (1.f + __expf(-v11));
            }
            *reinterpret_cast<float2*>(outF + (size_t)rowA * N + col)      = p0;
            *reinterpret_cast<float2*>(outF + (size_t)(rowA + 8) * N + col) = p1;
        }
    }
}

// ---------------- host ----------------
extern "C" void kernel_launch(void* const* d_in, const int* in_sizes, int n_in,
                              void* d_out, int out_size) {
    const float* x  = (const float*)d_in[0];
    const float* w1 = (const float*)d_in[1];
    const float* b1 = (const float*)d_in[2];
    const float* w2 = (const float*)d_in[3];
    const float* b2 = (const float*)d_in[4];
    const float* w3 = (const float*)d_in[5];
    const float* b3 = (const float*)d_in[6];

    void *pw1, *pw2, *pw3, *pqa, *pqb, *pact, *psum;
    cudaGetSymbolAddress(&pw1, g_w1q);
    cudaGetSymbolAddress(&pw2, g_w2q);
    cudaGetSymbolAddress(&pw3, g_w3q);
    cudaGetSymbolAddress(&pqa, g_qa);
    cudaGetSymbolAddress(&pqb, g_qb);
    cudaGetSymbolAddress(&pact, g_act);
    cudaGetSymbolAddress(&psum, g_sum);
    float* sum = (float*)psum;

    // 1. quantize weights (dual-scale signs) + |w| sums
    sign_quant_kernel<<<2048, 256>>>((const float4*)w1, (int8_t*)pw1, HIDDEN * K / 4, 0);
    sign_quant_kernel<<<2048, 256>>>((const float4*)w2, (int8_t*)pw2, HIDDEN * K / 4, 1);
    sign_quant_kernel<<<2048, 256>>>((const float4*)w3, (int8_t*)pw3, OUT_SIZE * K / 4, 2);
    finalize_sum_kernel<<<3, 1024>>>();

    // 2. quantize x per-row into digits
    quant_rows_kernel<<<BATCH, 256>>>(x, (int8_t*)pqa);

    cudaFuncSetAttribute(gemm_i8<0>, cudaFuncAttributeMaxDynamicSharedMemorySize, SMEM_TOTAL);
    cudaFuncSetAttribute(gemm_i8<1>, cudaFuncAttributeMaxDynamicSharedMemorySize, SMEM_TOTAL);

    // 3. layer 1
    gemm_i8<0><<<dim3(HIDDEN / 128, BATCH / 128), 256, SMEM_TOTAL>>>(
        (const int8_t*)pqa, (const int8_t*)pw1, b1, sum + 0,
        1.0f / ((float)HIDDEN * (float)IN_SIZE), HIDDEN, (float*)pact);
    quant_rows_kernel<<<BATCH, 256>>>((const float*)pact, (int8_t*)pqb);

    // 4. layer 2
    gemm_i8<0><<<dim3(HIDDEN / 128, BATCH / 128), 256, SMEM_TOTAL>>>(
        (const int8_t*)pqb, (const int8_t*)pw2, b2, sum + 1,
        1.0f / ((float)HIDDEN * (float)HIDDEN), HIDDEN, (float*)pact);
    quant_rows_kernel<<<BATCH, 256>>>((const float*)pact, (int8_t*)pqa);

    // 5. layer 3
    gemm_i8<1><<<dim3(OUT_SIZE / 128, BATCH / 128), 256, SMEM_TOTAL>>>(
        (const int8_t*)pqa, (const int8_t*)pw3, b3, sum + 2,
        1.0f / ((float)OUT_SIZE * (float)HIDDEN), OUT_SIZE, (float*)d_out);
}

// round 4
// speedup vs baseline: 2.6266x; 2.6266x over previous
#include <cuda_runtime.h>
#include <cuda_bf16.h>
#include <cstdint>

using bf16 = __nv_bfloat16;

// Problem dims
constexpr int BATCH    = 8192;
constexpr int IN_SIZE  = 4096;
constexpr int HIDDEN   = 4096;
constexpr int OUT_SIZE = 1024;

// GEMM tiling
constexpr int BK = 64;                        // bf16 elems per stage
constexpr int STAGES = 3;
constexpr int ROW_ELEMS  = 72;                // 64 data + 8 pad bf16 (144B pitch)
constexpr int TILE_ELEMS = 128 * ROW_ELEMS;   // 9216 bf16
constexpr int STAGE_ELEMS = 3 * TILE_ELEMS;   // Ahi, Alo, B
constexpr int SMEM_BYTES = STAGES * STAGE_ELEMS * 2;  // 165888 B

// ---------------- static device scratch ----------------
__device__ bf16 g_w1s[HIDDEN * IN_SIZE];
__device__ bf16 g_w2s[HIDDEN * HIDDEN];
__device__ bf16 g_w3s[OUT_SIZE * HIDDEN];
__device__ bf16 g_ahi[BATCH * IN_SIZE];
__device__ bf16 g_alo[BATCH * IN_SIZE];
__device__ bf16 g_bhi[BATCH * HIDDEN];
__device__ bf16 g_blo[BATCH * HIDDEN];
__device__ float g_part[3 * 2048];
__device__ float g_sum[3];

// ---------------- PTX helpers ----------------
__device__ __forceinline__ uint32_t sptr(const void* p) {
    return (uint32_t)__cvta_generic_to_shared(p);
}
__device__ __forceinline__ void cp16(const bf16* dst_smem, const bf16* src_gmem) {
    uint32_t d = sptr(dst_smem);
    asm volatile("cp.async.cg.shared.global [%0], [%1], 16;\n" :: "r"(d), "l"(src_gmem));
}
__device__ __forceinline__ void ldsm4(uint32_t* r, uint32_t addr) {
    asm volatile("ldmatrix.sync.aligned.m8n8.x4.shared.b16 {%0,%1,%2,%3}, [%4];"
                 : "=r"(r[0]), "=r"(r[1]), "=r"(r[2]), "=r"(r[3]) : "r"(addr));
}
__device__ __forceinline__ void mma_bf16(float* d, const uint32_t* a, const uint32_t* b) {
    asm volatile(
        "mma.sync.aligned.m16n8k16.row.col.f32.bf16.bf16.f32 "
        "{%0,%1,%2,%3}, {%4,%5,%6,%7}, {%8,%9}, {%0,%1,%2,%3};"
        : "+f"(d[0]), "+f"(d[1]), "+f"(d[2]), "+f"(d[3])
        : "r"(a[0]), "r"(a[1]), "r"(a[2]), "r"(a[3]), "r"(b[0]), "r"(b[1]));
}

// ---------------- prep kernels ----------------
__global__ void sign_reduce_kernel(const float4* __restrict__ w4,
                                   __nv_bfloat162* __restrict__ ws2,
                                   int n4, int layer) {
    float s = 0.f;
    for (int i = blockIdx.x * blockDim.x + threadIdx.x; i < n4; i += gridDim.x * blockDim.x) {
        float4 v = w4[i];
        s += fabsf(v.x) + fabsf(v.y) + fabsf(v.z) + fabsf(v.w);
        bf16 s0 = __float2bfloat16((v.x > 0.f) ? 1.f : ((v.x < 0.f) ? -1.f : 0.f));
        bf16 s1 = __float2bfloat16((v.y > 0.f) ? 1.f : ((v.y < 0.f) ? -1.f : 0.f));
        bf16 s2 = __float2bfloat16((v.z > 0.f) ? 1.f : ((v.z < 0.f) ? -1.f : 0.f));
        bf16 s3 = __float2bfloat16((v.w > 0.f) ? 1.f : ((v.w < 0.f) ? -1.f : 0.f));
        ws2[2 * i]     = __halves2bfloat162(s0, s1);
        ws2[2 * i + 1] = __halves2bfloat162(s2, s3);
    }
    __shared__ float red[256];
    red[threadIdx.x] = s;
    __syncthreads();
    for (int o = 128; o > 0; o >>= 1) {
        if (threadIdx.x < o) red[threadIdx.x] += red[threadIdx.x + o];
        __syncthreads();
    }
    if (threadIdx.x == 0) g_part[layer * 2048 + blockIdx.x] = red[0];
}

__global__ void finalize_sum_kernel() {
    __shared__ float red[1024];
    int l = blockIdx.x, t = threadIdx.x;
    red[t] = g_part[l * 2048 + t] + g_part[l * 2048 + 1024 + t];
    __syncthreads();
    for (int o = 512; o > 0; o >>= 1) {
        if (t < o) red[t] += red[t + o];
        __syncthreads();
    }
    if (t == 0) g_sum[l] = red[0];
}

__global__ void split_kernel(const float4* __restrict__ x4,
                             __nv_bfloat162* __restrict__ hi2,
                             __nv_bfloat162* __restrict__ lo2, int n4) {
    for (int i = blockIdx.x * blockDim.x + threadIdx.x; i < n4; i += gridDim.x * blockDim.x) {
        float4 v = x4[i];
        bf16 h0 = __float2bfloat16(v.x), h1 = __float2bfloat16(v.y);
        bf16 h2 = __float2bfloat16(v.z), h3 = __float2bfloat16(v.w);
        bf16 l0 = __float2bfloat16(v.x - __bfloat162float(h0));
        bf16 l1 = __float2bfloat16(v.y - __bfloat162float(h1));
        bf16 l2 = __float2bfloat16(v.z - __bfloat162float(h2));
        bf16 l3 = __float2bfloat16(v.w - __bfloat162float(h3));
        hi2[2 * i]     = __halves2bfloat162(h0, h1);
        hi2[2 * i + 1] = __halves2bfloat162(h2, h3);
        lo2[2 * i]     = __halves2bfloat162(l0, l1);
        lo2[2 * i + 1] = __halves2bfloat162(l2, l3);
    }
}

// ---------------- fused binarized GEMM (bf16 hi/lo, BK=64, frag double-buffer) ----------------
template <int EPI>
__global__ void __launch_bounds__(256, 1) gemm_bwn(
    const bf16* __restrict__ Ahi, const bf16* __restrict__ Alo,
    const bf16* __restrict__ Bs,
    const float* __restrict__ bias, const float* __restrict__ sumAbs, float invCnt,
    int K, int N,
    bf16* __restrict__ oHi, bf16* __restrict__ oLo, float* __restrict__ oF) {
    extern __shared__ bf16 smem[];
    const int tid  = threadIdx.x;
    const int lane = tid & 31;
    const int warp = tid >> 5;
    const int wm = warp & 3;   // 4 warps along M (32 rows each)
    const int wn = warp >> 2;  // 2 warps along N (64 cols each)
    const int bm = blockIdx.y, bn = blockIdx.x;
    const int KT = K / BK;

    const bf16* gAhi = Ahi + (size_t)bm * 128 * K;
    const bf16* gAlo = Alo + (size_t)bm * 128 * K;
    const bf16* gB   = Bs  + (size_t)bn * 128 * K;

    const int crow = tid >> 3;        // 0..31
    const int ccol = (tid & 7) * 8;   // bf16 elems, 16B chunks (64 elems/row)

    auto issue = [&](int kt, int stage) {
        bf16* s = smem + stage * STAGE_ELEMS;
        bf16* sl = s + TILE_ELEMS;
        bf16* sb = s + 2 * TILE_ELEMS;
        const int kof = kt * BK;
#pragma unroll
        for (int rr = 0; rr < 4; rr++) {
            const int row = rr * 32 + crow;
            cp16(s  + row * ROW_ELEMS + ccol, gAhi + (size_t)row * K + kof + ccol);
            cp16(sl + row * ROW_ELEMS + ccol, gAlo + (size_t)row * K + kof + ccol);
            cp16(sb + row * ROW_ELEMS + ccol, gB   + (size_t)row * K + kof + ccol);
        }
    };

    float acc[2][8][4];
#pragma unroll
    for (int i = 0; i < 2; i++)
#pragma unroll
        for (int j = 0; j < 8; j++)
#pragma unroll
            for (int v = 0; v < 4; v++) acc[i][j][v] = 0.f;

    // precomputed in-tile ldsm offsets (elems)
    const int a_off = (wm * 32 + (lane & 15)) * ROW_ELEMS + (lane >> 4) * 8;
    const int b_off = (wn * 64 + ((lane >> 4) & 1) * 8 + (lane & 7)) * ROW_ELEMS
                    + ((lane >> 3) & 1) * 8;

    uint32_t ah[2][2][4], al[2][2][4], bb[2][8][2];  // [buf][...]

    auto load_frag = [&](int stage, int ks, int buf) {
        const bf16* sA  = smem + stage * STAGE_ELEMS;
        const bf16* sAl = sA + TILE_ELEMS;
        const bf16* sB  = sA + 2 * TILE_ELEMS;
        const int kc = ks * 16;
#pragma unroll
        for (int i = 0; i < 2; i++) {
            ldsm4(ah[buf][i], sptr(sA  + a_off + i * 16 * ROW_ELEMS + kc));
            ldsm4(al[buf][i], sptr(sAl + a_off + i * 16 * ROW_ELEMS + kc));
        }
#pragma unroll
        for (int jj = 0; jj < 4; jj++) {
            uint32_t r[4];
            ldsm4(r, sptr(sB + b_off + jj * 16 * ROW_ELEMS + kc));
            bb[buf][2 * jj][0] = r[0]; bb[buf][2 * jj][1] = r[1];
            bb[buf][2 * jj + 1][0] = r[2]; bb[buf][2 * jj + 1][1] = r[3];
        }
    };

    auto mma_all = [&](int buf) {
#pragma unroll
        for (int i = 0; i < 2; i++)
#pragma unroll
            for (int j = 0; j < 8; j++) {
                mma_bf16(acc[i][j], ah[buf][i], bb[buf][j]);
                mma_bf16(acc[i][j], al[buf][i], bb[buf][j]);
            }
    };

    // prologue: stages 0,1
    issue(0, 0);
    asm volatile("cp.async.commit_group;" ::: "memory");
    issue(1, 1);
    asm volatile("cp.async.commit_group;" ::: "memory");

    for (int kt = 0; kt < KT; kt++) {
        const int stage = kt % STAGES;
        asm volatile("cp.async.wait_group 1;" ::: "memory");
        __syncthreads();
        const int kn = kt + 2;
        if (kn < KT) issue(kn, kn % STAGES);
        asm volatile("cp.async.commit_group;" ::: "memory");

        // 4 ks slices, fragment double-buffered
        load_frag(stage, 0, 0);
#pragma unroll
        for (int ks = 0; ks < 4; ks++) {
            if (ks < 3) load_frag(stage, ks + 1, (ks + 1) & 1);
            mma_all(ks & 1);
        }
    }

    // ---------------- epilogue ----------------
    const float alpha = __ldg(sumAbs) * invCnt;
    const int r0 = bm * 128 + wm * 32 + (lane >> 2);
    const int c0 = bn * 128 + wn * 64 + (lane & 3) * 2;
#pragma unroll
    for (int i = 0; i < 2; i++) {
#pragma unroll
        for (int j = 0; j < 8; j++) {
            int row = r0 + i * 16;
            int col = c0 + j * 8;
            float bx = __ldg(bias + col), by = __ldg(bias + col + 1);
            float v00 = acc[i][j][0] * alpha + bx;
            float v01 = acc[i][j][1] * alpha + by;
            float v10 = acc[i][j][2] * alpha + bx;
            float v11 = acc[i][j][3] * alpha + by;
            if (EPI == 0) {
                v00 = fmaxf(v00, 0.f); v01 = fmaxf(v01, 0.f);
                v10 = fmaxf(v10, 0.f); v11 = fmaxf(v11, 0.f);
                bf16 h00 = __float2bfloat16(v00), h01 = __float2bfloat16(v01);
                bf16 h10 = __float2bfloat16(v10), h11 = __float2bfloat16(v11);
                bf16 l00 = __float2bfloat16(v00 - __bfloat162float(h00));
                bf16 l01 = __float2bfloat16(v01 - __bfloat162float(h01));
                bf16 l10 = __float2bfloat16(v10 - __bfloat162float(h10));
                bf16 l11 = __float2bfloat16(v11 - __bfloat162float(h11));
                size_t i0 = (size_t)row * N + col;
                size_t i1 = (size_t)(row + 8) * N + col;
                *reinterpret_cast<__nv_bfloat162*>(oHi + i0) = __halves2bfloat162(h00, h01);
                *reinterpret_cast<__nv_bfloat162*>(oHi + i1) = __halves2bfloat162(h10, h11);
                *reinterpret_cast<__nv_bfloat162*>(oLo + i0) = __halves2bfloat162(l00, l01);
                *reinterpret_cast<__nv_bfloat162*>(oLo + i1) = __halves2bfloat162(l10, l11);
            } else {
                float2 s0, s1;
                s0.x = 1.f / (1.f + __expf(-v00));
                s0.y = 1.f / (1.f + __expf(-v01));
                s1.x = 1.f / (1.f + __expf(-v10));
                s1.y = 1.f / (1.f + __expf(-v11));
                *reinterpret_cast<float2*>(oF + (size_t)row * N + col)       = s0;
                *reinterpret_cast<float2*>(oF + (size_t)(row + 8) * N + col) = s1;
            }
        }
    }
}

// ---------------- host launch ----------------
extern "C" void kernel_launch(void* const* d_in, const int* in_sizes, int n_in,
                              void* d_out, int out_size) {
    const float* x  = (const float*)d_in[0];
    const float* w1 = (const float*)d_in[1];
    const float* b1 = (const float*)d_in[2];
    const float* w2 = (const float*)d_in[3];
    const float* b2 = (const float*)d_in[4];
    const float* w3 = (const float*)d_in[5];
    const float* b3 = (const float*)d_in[6];

    void *pw1, *pw2, *pw3, *pahi, *palo, *pbhi, *pblo, *psum;
    cudaGetSymbolAddress(&pw1, g_w1s);
    cudaGetSymbolAddress(&pw2, g_w2s);
    cudaGetSymbolAddress(&pw3, g_w3s);
    cudaGetSymbolAddress(&pahi, g_ahi);
    cudaGetSymbolAddress(&palo, g_alo);
    cudaGetSymbolAddress(&pbhi, g_bhi);
    cudaGetSymbolAddress(&pblo, g_blo);
    cudaGetSymbolAddress(&psum, g_sum);
    float* sum = (float*)psum;

    sign_reduce_kernel<<<2048, 256>>>((const float4*)w1, (__nv_bfloat162*)pw1,
                                      HIDDEN * IN_SIZE / 4, 0);
    sign_reduce_kernel<<<2048, 256>>>((const float4*)w2, (__nv_bfloat162*)pw2,
                                      HIDDEN * HIDDEN / 4, 1);
    sign_reduce_kernel<<<2048, 256>>>((const float4*)w3, (__nv_bfloat162*)pw3,
                                      OUT_SIZE * HIDDEN / 4, 2);
    finalize_sum_kernel<<<3, 1024>>>();

    split_kernel<<<2048, 256>>>((const float4*)x, (__nv_bfloat162*)pahi,
                                (__nv_bfloat162*)palo, BATCH * IN_SIZE / 4);

    cudaFuncSetAttribute(gemm_bwn<0>, cudaFuncAttributeMaxDynamicSharedMemorySize, SMEM_BYTES);
    cudaFuncSetAttribute(gemm_bwn<1>, cudaFuncAttributeMaxDynamicSharedMemorySize, SMEM_BYTES);

    gemm_bwn<0><<<dim3(HIDDEN / 128, BATCH / 128), 256, SMEM_BYTES>>>(
        (const bf16*)pahi, (const bf16*)palo, (const bf16*)pw1,
        b1, sum + 0, 1.0f / ((float)HIDDEN * (float)IN_SIZE),
        IN_SIZE, HIDDEN, (bf16*)pbhi, (bf16*)pblo, nullptr);

    gemm_bwn<0><<<dim3(HIDDEN / 128, BATCH / 128), 256, SMEM_BYTES>>>(
        (const bf16*)pbhi, (const bf16*)pblo, (const bf16*)pw2,
        b2, sum + 1, 1.0f / ((float)HIDDEN * (float)HIDDEN),
        HIDDEN, HIDDEN, (bf16*)pahi, (bf16*)palo, nullptr);

    gemm_bwn<1><<<dim3(OUT_SIZE / 128, BATCH / 128), 256, SMEM_BYTES>>>(
        (const bf16*)pahi, (const bf16*)palo, (const bf16*)pw3,
        b3, sum + 2, 1.0f / ((float)OUT_SIZE * (float)HIDDEN),
        HIDDEN, OUT_SIZE, nullptr, nullptr, (float*)d_out);
}

// round 5
// speedup vs baseline: 4.3950x; 1.6732x over previous
#include <cuda_runtime.h>
#include <cuda_fp16.h>
#include <cstdint>

using f16 = __half;

// Problem dims
constexpr int BATCH    = 8192;
constexpr int IN_SIZE  = 4096;
constexpr int HIDDEN   = 4096;
constexpr int OUT_SIZE = 1024;

// GEMM tiling
constexpr int BK = 64;                        // f16 elems per stage
constexpr int STAGES = 4;
constexpr int ROW_ELEMS  = 72;                // 64 data + 8 pad f16 (144B pitch)
constexpr int TILE_ELEMS = 128 * ROW_ELEMS;   // 9216 f16
constexpr int STAGE_ELEMS = 2 * TILE_ELEMS;   // A, B
constexpr int SMEM_BYTES = STAGES * STAGE_ELEMS * 2;  // 147456 B

// ---------------- static device scratch ----------------
__device__ f16 g_w1s[HIDDEN * IN_SIZE];
__device__ f16 g_w2s[HIDDEN * HIDDEN];
__device__ f16 g_w3s[OUT_SIZE * HIDDEN];
__device__ f16 g_a[BATCH * IN_SIZE];
__device__ f16 g_b[BATCH * HIDDEN];
__device__ float g_part[3 * 2048];
__device__ float g_sum[3];

// ---------------- PTX helpers ----------------
__device__ __forceinline__ uint32_t sptr(const void* p) {
    return (uint32_t)__cvta_generic_to_shared(p);
}
__device__ __forceinline__ void cp16(const f16* dst_smem, const f16* src_gmem) {
    uint32_t d = sptr(dst_smem);
    asm volatile("cp.async.cg.shared.global [%0], [%1], 16;\n" :: "r"(d), "l"(src_gmem));
}
__device__ __forceinline__ void ldsm4(uint32_t* r, uint32_t addr) {
    asm volatile("ldmatrix.sync.aligned.m8n8.x4.shared.b16 {%0,%1,%2,%3}, [%4];"
                 : "=r"(r[0]), "=r"(r[1]), "=r"(r[2]), "=r"(r[3]) : "r"(addr));
}
__device__ __forceinline__ void mma_f16(float* d, const uint32_t* a, const uint32_t* b) {
    asm volatile(
        "mma.sync.aligned.m16n8k16.row.col.f32.f16.f16.f32 "
        "{%0,%1,%2,%3}, {%4,%5,%6,%7}, {%8,%9}, {%0,%1,%2,%3};"
        : "+f"(d[0]), "+f"(d[1]), "+f"(d[2]), "+f"(d[3])
        : "r"(a[0]), "r"(a[1]), "r"(a[2]), "r"(a[3]), "r"(b[0]), "r"(b[1]));
}

// ---------------- prep kernels ----------------
__global__ void sign_reduce_kernel(const float4* __restrict__ w4,
                                   __half2* __restrict__ ws2,
                                   int n4, int layer) {
    float s = 0.f;
    for (int i = blockIdx.x * blockDim.x + threadIdx.x; i < n4; i += gridDim.x * blockDim.x) {
        float4 v = w4[i];
        s += fabsf(v.x) + fabsf(v.y) + fabsf(v.z) + fabsf(v.w);
        f16 s0 = __float2half((v.x > 0.f) ? 1.f : ((v.x < 0.f) ? -1.f : 0.f));
        f16 s1 = __float2half((v.y > 0.f) ? 1.f : ((v.y < 0.f) ? -1.f : 0.f));
        f16 s2 = __float2half((v.z > 0.f) ? 1.f : ((v.z < 0.f) ? -1.f : 0.f));
        f16 s3 = __float2half((v.w > 0.f) ? 1.f : ((v.w < 0.f) ? -1.f : 0.f));
        ws2[2 * i]     = __halves2half2(s0, s1);
        ws2[2 * i + 1] = __halves2half2(s2, s3);
    }
    __shared__ float red[256];
    red[threadIdx.x] = s;
    __syncthreads();
    for (int o = 128; o > 0; o >>= 1) {
        if (threadIdx.x < o) red[threadIdx.x] += red[threadIdx.x + o];
        __syncthreads();
    }
    if (threadIdx.x == 0) g_part[layer * 2048 + blockIdx.x] = red[0];
}

__global__ void finalize_sum_kernel() {
    __shared__ float red[1024];
    int l = blockIdx.x, t = threadIdx.x;
    red[t] = g_part[l * 2048 + t] + g_part[l * 2048 + 1024 + t];
    __syncthreads();
    for (int o = 512; o > 0; o >>= 1) {
        if (t < o) red[t] += red[t + o];
        __syncthreads();
    }
    if (t == 0) g_sum[l] = red[0];
}

// f32 x -> f16
__global__ void convert_kernel(const float4* __restrict__ x4,
                               __half2* __restrict__ h2, int n4) {
    for (int i = blockIdx.x * blockDim.x + threadIdx.x; i < n4; i += gridDim.x * blockDim.x) {
        float4 v = x4[i];
        h2[2 * i]     = __halves2half2(__float2half(v.x), __float2half(v.y));
        h2[2 * i + 1] = __halves2half2(__float2half(v.z), __float2half(v.w));
    }
}

// ---------------- fused binarized GEMM (fp16, BK=64, 4 stages, frag double-buffer) ----------------
// Y[M,N] = alpha * (A[M,K] @ S[N,K]^T) + bias ; EPI0: relu -> f16, EPI1: sigmoid -> f32
template <int EPI>
__global__ void __launch_bounds__(256, 1) gemm_bwn(
    const f16* __restrict__ A, const f16* __restrict__ Bs,
    const float* __restrict__ bias, const float* __restrict__ sumAbs, float invCnt,
    int K, int N,
    f16* __restrict__ oH, float* __restrict__ oF) {
    extern __shared__ f16 smem[];
    const int tid  = threadIdx.x;
    const int lane = tid & 31;
    const int warp = tid >> 5;
    const int wm = warp & 3;   // 4 warps along M (32 rows each)
    const int wn = warp >> 2;  // 2 warps along N (64 cols each)
    const int bm = blockIdx.y, bn = blockIdx.x;
    const int KT = K / BK;

    const f16* gA = A  + (size_t)bm * 128 * K;
    const f16* gB = Bs + (size_t)bn * 128 * K;

    const int crow = tid >> 3;        // 0..31
    const int ccol = (tid & 7) * 8;   // 16B chunks (64 elems/row)

    auto issue = [&](int kt, int stage) {
        f16* sa = smem + stage * STAGE_ELEMS;
        f16* sb = sa + TILE_ELEMS;
        const int kof = kt * BK;
#pragma unroll
        for (int rr = 0; rr < 4; rr++) {
            const int row = rr * 32 + crow;
            cp16(sa + row * ROW_ELEMS + ccol, gA + (size_t)row * K + kof + ccol);
            cp16(sb + row * ROW_ELEMS + ccol, gB + (size_t)row * K + kof + ccol);
        }
    };

    float acc[2][8][4];
#pragma unroll
    for (int i = 0; i < 2; i++)
#pragma unroll
        for (int j = 0; j < 8; j++)
#pragma unroll
            for (int v = 0; v < 4; v++) acc[i][j][v] = 0.f;

    const int a_off = (wm * 32 + (lane & 15)) * ROW_ELEMS + (lane >> 4) * 8;
    const int b_off = (wn * 64 + ((lane >> 4) & 1) * 8 + (lane & 7)) * ROW_ELEMS
                    + ((lane >> 3) & 1) * 8;

    uint32_t af[2][2][4], bf[2][8][2];  // [buf][...]

    auto load_frag = [&](int stage, int ks, int buf) {
        const f16* sA = smem + stage * STAGE_ELEMS;
        const f16* sB = sA + TILE_ELEMS;
        const int kc = ks * 16;
#pragma unroll
        for (int i = 0; i < 2; i++)
            ldsm4(af[buf][i], sptr(sA + a_off + i * 16 * ROW_ELEMS + kc));
#pragma unroll
        for (int jj = 0; jj < 4; jj++) {
            uint32_t r[4];
            ldsm4(r, sptr(sB + b_off + jj * 16 * ROW_ELEMS + kc));
            bf[buf][2 * jj][0] = r[0]; bf[buf][2 * jj][1] = r[1];
            bf[buf][2 * jj + 1][0] = r[2]; bf[buf][2 * jj + 1][1] = r[3];
        }
    };

    auto mma_all = [&](int buf) {
#pragma unroll
        for (int i = 0; i < 2; i++)
#pragma unroll
            for (int j = 0; j < 8; j++)
                mma_f16(acc[i][j], af[buf][i], bf[buf][j]);
    };

    // prologue: 3 stages ahead
    issue(0, 0);
    asm volatile("cp.async.commit_group;" ::: "memory");
    issue(1, 1);
    asm volatile("cp.async.commit_group;" ::: "memory");
    issue(2, 2);
    asm volatile("cp.async.commit_group;" ::: "memory");

    for (int kt = 0; kt < KT; kt++) {
        const int stage = kt & (STAGES - 1);
        asm volatile("cp.async.wait_group 2;" ::: "memory");
        __syncthreads();
        const int kn = kt + 3;
        if (kn < KT) issue(kn, kn & (STAGES - 1));
        asm volatile("cp.async.commit_group;" ::: "memory");

        load_frag(stage, 0, 0);
#pragma unroll
        for (int ks = 0; ks < 4; ks++) {
            if (ks < 3) load_frag(stage, ks + 1, (ks + 1) & 1);
            mma_all(ks & 1);
        }
    }

    // ---------------- epilogue ----------------
    const float alpha = __ldg(sumAbs) * invCnt;
    const int r0 = bm * 128 + wm * 32 + (lane >> 2);
    const int c0 = bn * 128 + wn * 64 + (lane & 3) * 2;
#pragma unroll
    for (int i = 0; i < 2; i++) {
#pragma unroll
        for (int j = 0; j < 8; j++) {
            int row = r0 + i * 16;
            int col = c0 + j * 8;
            float bx = __ldg(bias + col), by = __ldg(bias + col + 1);
            float v00 = acc[i][j][0] * alpha + bx;
            float v01 = acc[i][j][1] * alpha + by;
            float v10 = acc[i][j][2] * alpha + bx;
            float v11 = acc[i][j][3] * alpha + by;
            if (EPI == 0) {
                v00 = fmaxf(v00, 0.f); v01 = fmaxf(v01, 0.f);
                v10 = fmaxf(v10, 0.f); v11 = fmaxf(v11, 0.f);
                size_t i0 = (size_t)row * N + col;
                size_t i1 = (size_t)(row + 8) * N + col;
                *reinterpret_cast<__half2*>(oH + i0) =
                    __halves2half2(__float2half(v00), __float2half(v01));
                *reinterpret_cast<__half2*>(oH + i1) =
                    __halves2half2(__float2half(v10), __float2half(v11));
            } else {
                float2 s0, s1;
                s0.x = 1.f / (1.f + __expf(-v00));
                s0.y = 1.f / (1.f + __expf(-v01));
                s1.x = 1.f / (1.f + __expf(-v10));
                s1.y = 1.f / (1.f + __expf(-v11));
                *reinterpret_cast<float2*>(oF + (size_t)row * N + col)       = s0;
                *reinterpret_cast<float2*>(oF + (size_t)(row + 8) * N + col) = s1;
            }
        }
    }
}

// ---------------- host launch ----------------
extern "C" void kernel_launch(void* const* d_in, const int* in_sizes, int n_in,
                              void* d_out, int out_size) {
    const float* x  = (const float*)d_in[0];
    const float* w1 = (const float*)d_in[1];
    const float* b1 = (const float*)d_in[2];
    const float* w2 = (const float*)d_in[3];
    const float* b2 = (const float*)d_in[4];
    const float* w3 = (const float*)d_in[5];
    const float* b3 = (const float*)d_in[6];

    void *pw1, *pw2, *pw3, *pa, *pb, *psum;
    cudaGetSymbolAddress(&pw1, g_w1s);
    cudaGetSymbolAddress(&pw2, g_w2s);
    cudaGetSymbolAddress(&pw3, g_w3s);
    cudaGetSymbolAddress(&pa, g_a);
    cudaGetSymbolAddress(&pb, g_b);
    cudaGetSymbolAddress(&psum, g_sum);
    float* sum = (float*)psum;

    sign_reduce_kernel<<<2048, 256>>>((const float4*)w1, (__half2*)pw1,
                                      HIDDEN * IN_SIZE / 4, 0);
    sign_reduce_kernel<<<2048, 256>>>((const float4*)w2, (__half2*)pw2,
                                      HIDDEN * HIDDEN / 4, 1);
    sign_reduce_kernel<<<2048, 256>>>((const float4*)w3, (__half2*)pw3,
                                      OUT_SIZE * HIDDEN / 4, 2);
    finalize_sum_kernel<<<3, 1024>>>();

    convert_kernel<<<2048, 256>>>((const float4*)x, (__half2*)pa, BATCH * IN_SIZE / 4);

    cudaFuncSetAttribute(gemm_bwn<0>, cudaFuncAttributeMaxDynamicSharedMemorySize, SMEM_BYTES);
    cudaFuncSetAttribute(gemm_bwn<1>, cudaFuncAttributeMaxDynamicSharedMemorySize, SMEM_BYTES);

    gemm_bwn<0><<<dim3(HIDDEN / 128, BATCH / 128), 256, SMEM_BYTES>>>(
        (const f16*)pa, (const f16*)pw1, b1, sum + 0,
        1.0f / ((float)HIDDEN * (float)IN_SIZE),
        IN_SIZE, HIDDEN, (f16*)pb, nullptr);

    gemm_bwn<0><<<dim3(HIDDEN / 128, BATCH / 128), 256, SMEM_BYTES>>>(
        (const f16*)pb, (const f16*)pw2, b2, sum + 1,
        1.0f / ((float)HIDDEN * (float)HIDDEN),
        HIDDEN, HIDDEN, (f16*)pa, nullptr);

    gemm_bwn<1><<<dim3(OUT_SIZE / 128, BATCH / 128), 256, SMEM_BYTES>>>(
        (const f16*)pa, (const f16*)pw3, b3, sum + 2,
        1.0f / ((float)OUT_SIZE * (float)HIDDEN),
        HIDDEN, OUT_SIZE, nullptr, (float*)d_out);
}

// round 6
// speedup vs baseline: 4.9118x; 1.1176x over previous
#include <cuda_runtime.h>
#include <cuda_fp16.h>
#include <cstdint>

using f16 = __half;

// Problem dims
constexpr int BATCH    = 8192;
constexpr int IN_SIZE  = 4096;
constexpr int HIDDEN   = 4096;
constexpr int OUT_SIZE = 1024;

// GEMM tiling: CTA tile 256x128, warp tile 64x64, BK=64
constexpr int TM = 256;
constexpr int TN = 128;
constexpr int BK = 64;
constexpr int STAGES = 3;
constexpr int ROW_ELEMS  = 72;                    // 64 data + 8 pad f16 (144B pitch)
constexpr int A_ELEMS = TM * ROW_ELEMS;           // 18432
constexpr int B_ELEMS = TN * ROW_ELEMS;           // 9216
constexpr int STAGE_ELEMS = A_ELEMS + B_ELEMS;    // 27648
constexpr int SMEM_BYTES = STAGES * STAGE_ELEMS * 2;  // 165888 B

// ---------------- static device scratch ----------------
__device__ f16 g_w1s[HIDDEN * IN_SIZE];
__device__ f16 g_w2s[HIDDEN * HIDDEN];
__device__ f16 g_w3s[OUT_SIZE * HIDDEN];
__device__ f16 g_a[BATCH * IN_SIZE];
__device__ f16 g_b[BATCH * HIDDEN];
__device__ float g_part[3 * 2048];
__device__ float g_sum[3];

// ---------------- PTX helpers ----------------
__device__ __forceinline__ uint32_t sptr(const void* p) {
    return (uint32_t)__cvta_generic_to_shared(p);
}
__device__ __forceinline__ void cp16(const f16* dst_smem, const f16* src_gmem) {
    uint32_t d = sptr(dst_smem);
    asm volatile("cp.async.cg.shared.global [%0], [%1], 16;\n" :: "r"(d), "l"(src_gmem));
}
__device__ __forceinline__ void ldsm4(uint32_t* r, uint32_t addr) {
    asm volatile("ldmatrix.sync.aligned.m8n8.x4.shared.b16 {%0,%1,%2,%3}, [%4];"
                 : "=r"(r[0]), "=r"(r[1]), "=r"(r[2]), "=r"(r[3]) : "r"(addr));
}
__device__ __forceinline__ void mma_f16(float* d, const uint32_t* a, const uint32_t* b) {
    asm volatile(
        "mma.sync.aligned.m16n8k16.row.col.f32.f16.f16.f32 "
        "{%0,%1,%2,%3}, {%4,%5,%6,%7}, {%8,%9}, {%0,%1,%2,%3};"
        : "+f"(d[0]), "+f"(d[1]), "+f"(d[2]), "+f"(d[3])
        : "r"(a[0]), "r"(a[1]), "r"(a[2]), "r"(a[3]), "r"(b[0]), "r"(b[1]));
}

// ---------------- prep kernels ----------------
__global__ void sign_reduce_kernel(const float4* __restrict__ w4,
                                   __half2* __restrict__ ws2,
                                   int n4, int layer) {
    float s = 0.f;
    for (int i = blockIdx.x * blockDim.x + threadIdx.x; i < n4; i += gridDim.x * blockDim.x) {
        float4 v = w4[i];
        s += fabsf(v.x) + fabsf(v.y) + fabsf(v.z) + fabsf(v.w);
        f16 s0 = __float2half((v.x > 0.f) ? 1.f : ((v.x < 0.f) ? -1.f : 0.f));
        f16 s1 = __float2half((v.y > 0.f) ? 1.f : ((v.y < 0.f) ? -1.f : 0.f));
        f16 s2 = __float2half((v.z > 0.f) ? 1.f : ((v.z < 0.f) ? -1.f : 0.f));
        f16 s3 = __float2half((v.w > 0.f) ? 1.f : ((v.w < 0.f) ? -1.f : 0.f));
        ws2[2 * i]     = __halves2half2(s0, s1);
        ws2[2 * i + 1] = __halves2half2(s2, s3);
    }
    __shared__ float red[256];
    red[threadIdx.x] = s;
    __syncthreads();
    for (int o = 128; o > 0; o >>= 1) {
        if (threadIdx.x < o) red[threadIdx.x] += red[threadIdx.x + o];
        __syncthreads();
    }
    if (threadIdx.x == 0) g_part[layer * 2048 + blockIdx.x] = red[0];
}

__global__ void finalize_sum_kernel() {
    __shared__ float red[1024];
    int l = blockIdx.x, t = threadIdx.x;
    red[t] = g_part[l * 2048 + t] + g_part[l * 2048 + 1024 + t];
    __syncthreads();
    for (int o = 512; o > 0; o >>= 1) {
        if (t < o) red[t] += red[t + o];
        __syncthreads();
    }
    if (t == 0) g_sum[l] = red[0];
}

__global__ void convert_kernel(const float4* __restrict__ x4,
                               __half2* __restrict__ h2, int n4) {
    for (int i = blockIdx.x * blockDim.x + threadIdx.x; i < n4; i += gridDim.x * blockDim.x) {
        float4 v = x4[i];
        h2[2 * i]     = __halves2half2(__float2half(v.x), __float2half(v.y));
        h2[2 * i + 1] = __halves2half2(__float2half(v.z), __float2half(v.w));
    }
}

// ---------------- fused binarized GEMM (fp16, 256x128 CTA, 64x64 warp tiles) ----------------
template <int EPI>
__global__ void __launch_bounds__(256, 1) gemm_bwn(
    const f16* __restrict__ A, const f16* __restrict__ Bs,
    const float* __restrict__ bias, const float* __restrict__ sumAbs, float invCnt,
    int K, int N,
    f16* __restrict__ oH, float* __restrict__ oF) {
    extern __shared__ f16 smem[];
    const int tid  = threadIdx.x;
    const int lane = tid & 31;
    const int warp = tid >> 5;
    const int wm = warp & 3;   // 4 warp-rows of 64
    const int wn = warp >> 2;  // 2 warp-cols of 64
    const int bm = blockIdx.y, bn = blockIdx.x;
    const int KT = K / BK;

    const f16* gA = A  + (size_t)bm * TM * K;
    const f16* gB = Bs + (size_t)bn * TN * K;

    const int crow = tid >> 3;        // 0..31
    const int ccol = (tid & 7) * 8;   // 16B chunks (64 elems/row)

    auto issue = [&](int kt, int stage) {
        f16* sa = smem + stage * STAGE_ELEMS;
        f16* sb = sa + A_ELEMS;
        const int kof = kt * BK;
#pragma unroll
        for (int rr = 0; rr < 8; rr++) {
            const int row = rr * 32 + crow;
            cp16(sa + row * ROW_ELEMS + ccol, gA + (size_t)row * K + kof + ccol);
        }
#pragma unroll
        for (int rr = 0; rr < 4; rr++) {
            const int row = rr * 32 + crow;
            cp16(sb + row * ROW_ELEMS + ccol, gB + (size_t)row * K + kof + ccol);
        }
    };

    float acc[4][8][4];
#pragma unroll
    for (int i = 0; i < 4; i++)
#pragma unroll
        for (int j = 0; j < 8; j++)
#pragma unroll
            for (int v = 0; v < 4; v++) acc[i][j][v] = 0.f;

    const int a_off = (wm * 64 + (lane & 15)) * ROW_ELEMS + (lane >> 4) * 8;
    const int b_off = (wn * 64 + ((lane >> 4) & 1) * 8 + (lane & 7)) * ROW_ELEMS
                    + ((lane >> 3) & 1) * 8;

    // prologue: 2 stages ahead
    issue(0, 0);
    asm volatile("cp.async.commit_group;" ::: "memory");
    issue(1, 1);
    asm volatile("cp.async.commit_group;" ::: "memory");

    for (int kt = 0; kt < KT; kt++) {
        const int stage = kt % STAGES;
        asm volatile("cp.async.wait_group 1;" ::: "memory");
        __syncthreads();
        const int kn = kt + 2;
        if (kn < KT) issue(kn, kn % STAGES);
        asm volatile("cp.async.commit_group;" ::: "memory");

        const f16* sA = smem + stage * STAGE_ELEMS;
        const f16* sB = sA + A_ELEMS;
#pragma unroll
        for (int ks = 0; ks < 4; ks++) {
            const int kc = ks * 16;
            uint32_t af[4][4], bf[8][2];
#pragma unroll
            for (int i = 0; i < 4; i++)
                ldsm4(af[i], sptr(sA + a_off + i * 16 * ROW_ELEMS + kc));
#pragma unroll
            for (int jj = 0; jj < 4; jj++) {
                uint32_t r[4];
                ldsm4(r, sptr(sB + b_off + jj * 16 * ROW_ELEMS + kc));
                bf[2 * jj][0] = r[0]; bf[2 * jj][1] = r[1];
                bf[2 * jj + 1][0] = r[2]; bf[2 * jj + 1][1] = r[3];
            }
#pragma unroll
            for (int i = 0; i < 4; i++)
#pragma unroll
                for (int j = 0; j < 8; j++)
                    mma_f16(acc[i][j], af[i], bf[j]);
        }
    }

    // ---------------- epilogue ----------------
    const float alpha = __ldg(sumAbs) * invCnt;
    const int r0 = bm * TM + wm * 64 + (lane >> 2);
    const int c0 = bn * TN + wn * 64 + (lane & 3) * 2;
#pragma unroll
    for (int i = 0; i < 4; i++) {
#pragma unroll
        for (int j = 0; j < 8; j++) {
            int row = r0 + i * 16;
            int col = c0 + j * 8;
            float bx = __ldg(bias + col), by = __ldg(bias + col + 1);
            float v00 = acc[i][j][0] * alpha + bx;
            float v01 = acc[i][j][1] * alpha + by;
            float v10 = acc[i][j][2] * alpha + bx;
            float v11 = acc[i][j][3] * alpha + by;
            if (EPI == 0) {
                v00 = fmaxf(v00, 0.f); v01 = fmaxf(v01, 0.f);
                v10 = fmaxf(v10, 0.f); v11 = fmaxf(v11, 0.f);
                size_t i0 = (size_t)row * N + col;
                size_t i1 = (size_t)(row + 8) * N + col;
                *reinterpret_cast<__half2*>(oH + i0) =
                    __halves2half2(__float2half(v00), __float2half(v01));
                *reinterpret_cast<__half2*>(oH + i1) =
                    __halves2half2(__float2half(v10), __float2half(v11));
            } else {
                float2 s0, s1;
                s0.x = 1.f / (1.f + __expf(-v00));
                s0.y = 1.f / (1.f + __expf(-v01));
                s1.x = 1.f / (1.f + __expf(-v10));
                s1.y = 1.f / (1.f + __expf(-v11));
                *reinterpret_cast<float2*>(oF + (size_t)row * N + col)       = s0;
                *reinterpret_cast<float2*>(oF + (size_t)(row + 8) * N + col) = s1;
            }
        }
    }
}

// ---------------- host launch ----------------
extern "C" void kernel_launch(void* const* d_in, const int* in_sizes, int n_in,
                              void* d_out, int out_size) {
    const float* x  = (const float*)d_in[0];
    const float* w1 = (const float*)d_in[1];
    const float* b1 = (const float*)d_in[2];
    const float* w2 = (const float*)d_in[3];
    const float* b2 = (const float*)d_in[4];
    const float* w3 = (const float*)d_in[5];
    const float* b3 = (const float*)d_in[6];

    void *pw1, *pw2, *pw3, *pa, *pb, *psum;
    cudaGetSymbolAddress(&pw1, g_w1s);
    cudaGetSymbolAddress(&pw2, g_w2s);
    cudaGetSymbolAddress(&pw3, g_w3s);
    cudaGetSymbolAddress(&pa, g_a);
    cudaGetSymbolAddress(&pb, g_b);
    cudaGetSymbolAddress(&psum, g_sum);
    float* sum = (float*)psum;

    sign_reduce_kernel<<<2048, 256>>>((const float4*)w1, (__half2*)pw1,
                                      HIDDEN * IN_SIZE / 4, 0);
    sign_reduce_kernel<<<2048, 256>>>((const float4*)w2, (__half2*)pw2,
                                      HIDDEN * HIDDEN / 4, 1);
    sign_reduce_kernel<<<2048, 256>>>((const float4*)w3, (__half2*)pw3,
                                      OUT_SIZE * HIDDEN / 4, 2);
    finalize_sum_kernel<<<3, 1024>>>();

    convert_kernel<<<2048, 256>>>((const float4*)x, (__half2*)pa, BATCH * IN_SIZE / 4);

    cudaFuncSetAttribute(gemm_bwn<0>, cudaFuncAttributeMaxDynamicSharedMemorySize, SMEM_BYTES);
    cudaFuncSetAttribute(gemm_bwn<1>, cudaFuncAttributeMaxDynamicSharedMemorySize, SMEM_BYTES);

    gemm_bwn<0><<<dim3(HIDDEN / TN, BATCH / TM), 256, SMEM_BYTES>>>(
        (const f16*)pa, (const f16*)pw1, b1, sum + 0,
        1.0f / ((float)HIDDEN * (float)IN_SIZE),
        IN_SIZE, HIDDEN, (f16*)pb, nullptr);

    gemm_bwn<0><<<dim3(HIDDEN / TN, BATCH / TM), 256, SMEM_BYTES>>>(
        (const f16*)pb, (const f16*)pw2, b2, sum + 1,
        1.0f / ((float)HIDDEN * (float)HIDDEN),
        HIDDEN, HIDDEN, (f16*)pa, nullptr);

    gemm_bwn<1><<<dim3(OUT_SIZE / TN, BATCH / TM), 256, SMEM_BYTES>>>(
        (const f16*)pa, (const f16*)pw3, b3, sum + 2,
        1.0f / ((float)OUT_SIZE * (float)HIDDEN),
        HIDDEN, OUT_SIZE, nullptr, (float*)d_out);
}